// round 15
// baseline (speedup 1.0000x reference)
#include <cuda_runtime.h>
#include <cuda_bf16.h>
#include <cstdint>

// ---------------- model constants ----------------
#define BB   32
#define SS   8
#define DD   768
#define NEE  8192
#define TT_  8192
#define HH   80
#define LL   2048
#define SCC  256
#define HOPS 3
#define KSPLIT 4        // inside megakernel: 64 M-tiles x 4 k-splits = 256 CTAs

// ---------------- PTX helpers ----------------
__device__ __forceinline__ uint32_t smem_to_u32(const void* smem_ptr) {
    uint32_t addr;
    asm("{ .reg .u64 tmp; cvta.to.shared.u64 tmp, %1; cvt.u32.u64 %0, tmp; }"
        : "=r"(addr) : "l"(smem_ptr));
    return addr;
}
#define CP_ASYNC16(dst_u32, src_ptr) \
    asm volatile("cp.async.cg.shared.global [%0], [%1], 16;" :: "r"(dst_u32), "l"(src_ptr))
#define CP_COMMIT() asm volatile("cp.async.commit_group;" ::: "memory")
#define CP_WAIT(n)  asm volatile("cp.async.wait_group %0;" :: "n"(n) : "memory")
#define LDMATRIX_X4(r0, r1, r2, r3, addr) \
    asm volatile("ldmatrix.sync.aligned.m8n8.x4.shared.b16 {%0,%1,%2,%3}, [%4];" \
        : "=r"(r0), "=r"(r1), "=r"(r2), "=r"(r3) : "r"(addr))
#define MMA_FP8(c, a0, a1, a2, a3, b0, b1) \
    asm volatile("mma.sync.aligned.m16n8k32.row.col.f32.e4m3.e5m2.f32 " \
        "{%0,%1,%2,%3}, {%4,%5,%6,%7}, {%8,%9}, {%0,%1,%2,%3};" \
        : "+f"((c)[0]), "+f"((c)[1]), "+f"((c)[2]), "+f"((c)[3]) \
        : "r"(a0), "r"(a1), "r"(a2), "r"(a3), "r"(b0), "r"(b1))
#define CVT_E4M3X2(r, hi, lo) \
    asm("cvt.rn.satfinite.e4m3x2.f32 %0, %1, %2;" : "=h"(r) : "f"(hi), "f"(lo))
#define CVT_E5M2X2(r, hi, lo) \
    asm("cvt.rn.satfinite.e5m2x2.f32 %0, %1, %2;" : "=h"(r) : "f"(hi), "f"(lo))

#define SCALE_M 128.0f

// ---------------- scratch (device globals) ----------------
__device__ float g_sum1p[16][BB * SCC];
__device__ __align__(16) uint8_t g_xb[BB * NEE];
__device__ float g_y[KSPLIT][TT_ * BB];
__device__ __align__(16) uint8_t g_zb[BB * TT_];
__device__ float g_xp[HOPS][KSPLIT][BB * NEE];
__device__ float g_h[BB * 320];
__device__ float g_att[BB * 3];
__device__ __align__(16) uint8_t g_Msb[(size_t)TT_ * NEE];
__device__ __align__(16) uint8_t g_MoTb[(size_t)NEE * TT_];

// ---------------- software grid barrier (generation counting) ----------------
__device__ unsigned g_bar_cnt;
__device__ volatile unsigned g_bar_gen;

__device__ __forceinline__ void grid_barrier() {
    __syncthreads();
    if (threadIdx.x == 0) {
        unsigned gen = g_bar_gen;
        __threadfence();
        if (atomicAdd(&g_bar_cnt, 1u) == gridDim.x - 1) {
            g_bar_cnt = 0;
            __threadfence();
            g_bar_gen = gen + 1;
        } else {
            while (g_bar_gen == gen) { }
        }
        __threadfence();
    }
    __syncthreads();
}

// ---------------- Ms fp32 -> e4m3 x128 ----------------
__global__ void convMs_kernel(const float* __restrict__ Ms) {
    size_t i = (size_t)blockIdx.x * 256 + threadIdx.x;
    float4 v0 = ((const float4*)Ms)[2 * i], v1 = ((const float4*)Ms)[2 * i + 1];
    uint16_t u0, u1, u2, u3;
    CVT_E4M3X2(u0, v0.y * SCALE_M, v0.x * SCALE_M);
    CVT_E4M3X2(u1, v0.w * SCALE_M, v0.z * SCALE_M);
    CVT_E4M3X2(u2, v1.y * SCALE_M, v1.x * SCALE_M);
    CVT_E4M3X2(u3, v1.w * SCALE_M, v1.z * SCALE_M);
    uint2 o;
    o.x = (uint32_t)u0 | ((uint32_t)u1 << 16);
    o.y = (uint32_t)u2 | ((uint32_t)u3 << 16);
    ((uint2*)g_Msb)[i] = o;
}

// ---------------- convT v4: 128t x 128n tiles, conflict-free swizzle ----------------
#define CONVT_SMEM (128 * 129 * 4)
__global__ void __launch_bounds__(1024) convT_kernel(const float* __restrict__ Mo) {
    extern __shared__ float sh[];
    int t0 = blockIdx.x * 128, n0 = blockIdx.y * 128;
    int tx = threadIdx.x, ty = threadIdx.y;
    #pragma unroll
    for (int j = 0; j < 4; j++) {
        int c  = ty + 32 * j;
        int fc = (c >> 2) | ((c & 3) << 5);
        const float* src = Mo + (size_t)(t0 + c) * NEE + n0 + tx;
        #pragma unroll
        for (int nn = 0; nn < 4; nn++)
            sh[(nn * 32 + tx) * 129 + fc] = src[nn * 32];
    }
    __syncthreads();
    #pragma unroll
    for (int nn = 0; nn < 4; nn++) {
        int r = nn * 32 + ty;
        const float* row = sh + r * 129 + tx;
        float a = row[0]  * SCALE_M;
        float b = row[32] * SCALE_M;
        float c = row[64] * SCALE_M;
        float d = row[96] * SCALE_M;
        uint16_t p0, p1;
        CVT_E4M3X2(p0, b, a);
        CVT_E4M3X2(p1, d, c);
        ((uint32_t*)g_MoTb)[((size_t)(n0 + r) * TT_ + t0) / 4 + tx] =
            (uint32_t)p0 | ((uint32_t)p1 << 16);
    }
}

// ---------------- EmbeddingBag + span dot -> per-chunk partials ----------------
__device__ __forceinline__ int segsearch(const int* o, int l) {
    int lo = 0, hi = SCC;
    #pragma unroll
    for (int s = 0; s < 8; s++) {
        int mid = (lo + hi) >> 1;
        if (o[mid] <= l) lo = mid + 1; else hi = mid;
    }
    return lo - 1;
}

__global__ void __launch_bounds__(256) emb_dot_kernel(
        const float* __restrict__ emb,
        const int* __restrict__ ids,
        const float* __restrict__ att,
        const int* __restrict__ offs,
        const float* __restrict__ span_embs) {
    int b = blockIdx.x >> 4, chunk = blockIdx.x & 15;
    int tid = threadIdx.x, w = tid >> 5, lane = tid & 31;

    __shared__ float span_s[SS * DD];
    __shared__ int   offs_s[SCC];
    __shared__ float sum1_s[SCC];

    const float4* sp  = (const float4*)(span_embs + (size_t)b * SS * DD);
    float4*       sps = (float4*)span_s;
    #pragma unroll
    for (int i = 0; i < (SS * DD / 4) / 256; i++) sps[tid + i * 256] = sp[tid + i * 256];
    offs_s[tid] = offs[b * SCC + tid];
    sum1_s[tid] = 0.f;
    __syncthreads();

    const int bL   = b * LL;
    const int base = chunk * 128 + w * 16;

    #pragma unroll
    for (int i = 0; i < 16; i += 2) {
        int la = base + i, lb = base + i + 1;
        int   ida = ids[bL + la], idb = ids[bL + lb];
        float wa  = att[bL + la], wb  = att[bL + lb];
        int sega = segsearch(offs_s, la);
        int segb = segsearch(offs_s, lb);
        const float4* ra = (const float4*)(emb + (size_t)ida * DD);
        const float4* rb = (const float4*)(emb + (size_t)idb * DD);
        const float4* sa = (const float4*)(span_s + (sega & 7) * DD);
        const float4* sb = (const float4*)(span_s + (segb & 7) * DD);
        float da = 0.f, db = 0.f;
        #pragma unroll
        for (int j = 0; j < 6; j++) {
            float4 va = ra[lane + 32 * j];
            float4 xa = sa[lane + 32 * j];
            da += va.x * xa.x + va.y * xa.y + va.z * xa.z + va.w * xa.w;
            float4 vb = rb[lane + 32 * j];
            float4 xb = sb[lane + 32 * j];
            db += vb.x * xb.x + vb.y * xb.y + vb.z * xb.z + vb.w * xb.w;
        }
        #pragma unroll
        for (int o = 16; o; o >>= 1) {
            da += __shfl_xor_sync(0xffffffffu, da, o);
            db += __shfl_xor_sync(0xffffffffu, db, o);
        }
        if (lane == 0) {
            atomicAdd(&sum1_s[sega], wa * da);
            atomicAdd(&sum1_s[segb], wb * db);
        }
    }
    __syncthreads();
    g_sum1p[chunk][b * SCC + tid] = sum1_s[tid];
}

// ---------------- fused: softmax chain -> cand -> scatter -> NE softmax -> e5m2 ----------------
__global__ void cand_softmax_kernel(const float* __restrict__ span_embs,
                                    const float* __restrict__ span_w,
                                    const float* __restrict__ span_b,
                                    const int* __restrict__ qid_inds,
                                    float sx0) {
    int b = blockIdx.x, tid = threadIdx.x;
    __shared__ float ent[NEE];
    __shared__ float sh_sum1[256];
    __shared__ float sh_score[8];
    __shared__ float red[8];
    __shared__ float bc;

    #pragma unroll
    for (int i = 0; i < NEE / 256; i++) ent[tid + i * 256] = 0.f;

    int w = tid >> 5, lane = tid & 31;
    {
        const float* se = span_embs + ((size_t)b * SS + w) * DD;
        float d = 0.f;
        for (int i = lane; i < DD; i += 32) d += se[i] * span_w[i];
        #pragma unroll
        for (int o = 16; o; o >>= 1) d += __shfl_xor_sync(0xffffffffu, d, o);
        if (lane == 0) sh_score[w] = d + span_b[0];
    }
    {
        float s1v = 0.f;
        #pragma unroll
        for (int c2 = 0; c2 < 16; c2++) s1v += g_sum1p[c2][b * SCC + tid];
        sh_sum1[tid] = s1v;
    }
    __syncthreads();

    int c = tid & 31, s = tid >> 5;
    float m = -1e30f;
    #pragma unroll
    for (int s2 = 0; s2 < 8; s2++) m = fmaxf(m, sh_sum1[s2 * 32 + c]);
    float den = 0.f;
    #pragma unroll
    for (int s2 = 0; s2 < 8; s2++) den += expf(sh_sum1[s2 * 32 + c] - m);
    float sm1 = expf(sh_sum1[tid] - m) / den;
    float tv  = sh_score[s] * sm1;

    float bm = tv;
    #pragma unroll
    for (int o = 16; o; o >>= 1) bm = fmaxf(bm, __shfl_xor_sync(0xffffffffu, bm, o));
    if (lane == 0) red[w] = bm;
    __syncthreads();
    if (tid == 0) { float x = red[0]; for (int j = 1; j < 8; j++) x = fmaxf(x, red[j]); bc = x; }
    __syncthreads();
    bm = bc;
    float e = expf(tv - bm);
    float sm = e;
    #pragma unroll
    for (int o = 16; o; o >>= 1) sm += __shfl_xor_sync(0xffffffffu, sm, o);
    __syncthreads();
    if (lane == 0) red[w] = sm;
    __syncthreads();
    if (tid == 0) { float x = 0.f; for (int j = 0; j < 8; j++) x += red[j]; bc = x; }
    __syncthreads();
    float cand = e / bc;

    int qid = qid_inds[b * SCC + tid];
    if (qid < NEE) atomicAdd(&ent[qid], cand);
    __syncthreads();

    float v[NEE / 256];
    m = -1e30f;
    #pragma unroll
    for (int i = 0; i < NEE / 256; i++) { v[i] = ent[tid + i * 256]; m = fmaxf(m, v[i]); }
    #pragma unroll
    for (int o = 16; o; o >>= 1) m = fmaxf(m, __shfl_xor_sync(0xffffffffu, m, o));
    if (lane == 0) red[w] = m;
    __syncthreads();
    if (tid == 0) { float x = red[0]; for (int j = 1; j < 8; j++) x = fmaxf(x, red[j]); bc = x; }
    __syncthreads();
    m = bc;
    float ssum = 0.f;
    #pragma unroll
    for (int i = 0; i < NEE / 256; i++) { v[i] = expf(v[i] - m); ssum += v[i]; }
    #pragma unroll
    for (int o = 16; o; o >>= 1) ssum += __shfl_xor_sync(0xffffffffu, ssum, o);
    __syncthreads();
    if (lane == 0) red[w] = ssum;
    __syncthreads();
    if (tid == 0) { float x = 0.f; for (int j = 0; j < 8; j++) x += red[j]; bc = x; }
    __syncthreads();
    float inv = sx0 / bc;
    uint8_t* orow = g_xb + (size_t)b * NEE;
    #pragma unroll
    for (int i = 0; i < NEE / 256; i++) {
        uint16_t pk; CVT_E5M2X2(pk, 0.f, v[i] * inv);
        orow[tid + i * 256] = (uint8_t)(pk & 0xff);
    }
}

// ---------------- fused q + all 3 r-hops + att logits (256 threads) ----------------
__global__ void qr_kernel(const float* __restrict__ qn,
                          const float* __restrict__ rw,
                          const float* __restrict__ rb,
                          const float* __restrict__ iw0, const float* __restrict__ ib0,
                          const float* __restrict__ iw1, const float* __restrict__ ib1,
                          const float* __restrict__ iw2, const float* __restrict__ ib2,
                          const float* __restrict__ aw0, const float* __restrict__ ab0,
                          const float* __restrict__ aw1, const float* __restrict__ ab1,
                          const float* __restrict__ aw2, const float* __restrict__ ab2) {
    int b = blockIdx.x, tid = threadIdx.x;
    int w = tid >> 5, lane = tid & 31;
    __shared__ float h[320];
    __shared__ float v[80];

    const float* q = qn + (size_t)b * DD;
    for (int hh = w; hh < HH; hh += 8) {
        const float* r = rw + (size_t)hh * DD;
        float d = 0.f;
        for (int i = lane; i < DD; i += 32) d += q[i] * r[i];
        #pragma unroll
        for (int o = 16; o; o >>= 1) d += __shfl_xor_sync(0xffffffffu, d, o);
        if (lane == 0) h[hh] = d + rb[hh];
    }
    __syncthreads();

    const float* IW[3] = {iw0, iw1, iw2};
    const float* IB[3] = {ib0, ib1, ib2};
    const float* AW[3] = {aw0, aw1, aw2};
    const float* AB[3] = {ab0, ab1, ab2};

    for (int hop = 0; hop < HOPS; hop++) {
        int Wd = HH * (hop + 1);
        if (tid < 80) {
            float a = IB[hop][tid];
            const float* row = IW[hop] + (size_t)tid * Wd;
            for (int i = 0; i < Wd; i++) a += h[i] * row[i];
            v[tid] = a;
        } else if (tid == 80) {
            float a = AB[hop][0];
            for (int i = 0; i < Wd; i++) a += h[i] * AW[hop][i];
            g_att[b * 3 + hop] = a;
        }
        __syncthreads();
        float m = -1e30f;
        for (int i = 0; i < 80; i++) m = fmaxf(m, v[i]);
        float s = 0.f;
        for (int i = 0; i < 80; i++) s += expf(v[i] - m);
        if (tid < 80) h[Wd + tid] = expf(v[tid] - m) / s;
        __syncthreads();
    }
    for (int i = tid; i < 320; i += 256) g_h[b * 320 + i] = h[i];
}

// =====================================================================
// MEGAKERNEL: the entire hop loop in one launch.
//   256 CTAs x 256 threads, 80KB dyn smem, 2 CTAs/SM guaranteed -> all
//   CTAs co-resident -> software grid barrier is safe.
// =====================================================================
#define KCHUNK 128
#define NIT    16   // 2048 / 128 (KSPLIT=4)
#define SA_STAGE 16384
#define SB_STAGE 4096
#define GEMM_SMEM (4 * (SA_STAGE + SB_STAGE))   // 81920

template<bool TRANS_OUT>
__device__ void gemm_phase(const uint8_t* __restrict__ A,
                           const uint8_t* __restrict__ Bb,
                           float* __restrict__ Out,     // pre-offset by split
                           uint8_t* smem) {
    const uint32_t sAb = smem_to_u32(smem);
    const uint32_t sBb = sAb + 4 * SA_STAGE;

    const int tid  = threadIdx.x;
    const int wid  = tid >> 5;
    const int lane = tid & 31;
    const int mbase  = (blockIdx.x & 63) * 128;
    const int kstart = (blockIdx.x >> 6) * (KCHUNK * NIT);

    const uint8_t* Ab = A + (size_t)mbase * 8192 + kstart;
    const uint8_t* Bx = Bb + kstart;

    const int arow = tid >> 3;
    const int ac   = tid & 7;
    auto prefetch = [&](int it) {
        const int stage = it & 3;
        const uint32_t sa = sAb + stage * SA_STAGE;
        const uint32_t sb = sBb + stage * SB_STAGE;
        const uint8_t* ga = Ab + it * KCHUNK;
        #pragma unroll
        for (int j = 0; j < 4; j++) {
            int row = arow + j * 32;
            uint32_t dst = sa + row * 128 + ((ac ^ (row & 7)) << 4);
            CP_ASYNC16(dst, ga + (size_t)row * 8192 + ac * 16);
        }
        uint32_t dstb = sb + arow * 128 + ((ac ^ (arow & 7)) << 4);
        CP_ASYNC16(dstb, Bx + (size_t)arow * 8192 + it * KCHUNK + ac * 16);
    };

    prefetch(0); CP_COMMIT();
    prefetch(1); CP_COMMIT();
    prefetch(2); CP_COMMIT();

    float acc[4][4];
    #pragma unroll
    for (int j = 0; j < 4; j++)
        #pragma unroll
        for (int i = 0; i < 4; i++) acc[j][i] = 0.f;

    const int a_quad = lane >> 3;
    const int a_rloc = wid * 16 + (lane & 7) + (a_quad & 1) * 8;
    const int a_cke  = a_quad >> 1;
    const int b_n    = ((lane >> 4) * 8) + (lane & 7);
    const int b_cke  = (lane >> 3) & 1;

    for (int it = 0; it < NIT; it++) {
        if (it + 2 < NIT) { CP_WAIT(2); }
        else if (it + 1 < NIT) { CP_WAIT(1); }
        else { CP_WAIT(0); }
        __syncthreads();
        if (it + 3 < NIT) { prefetch(it + 3); CP_COMMIT(); }

        const int stage = it & 3;
        const uint32_t sa = sAb + stage * SA_STAGE;
        const uint32_t sb = sBb + stage * SB_STAGE;

        #pragma unroll
        for (int s = 0; s < 4; s++) {
            uint32_t a0, a1, a2, a3;
            {
                int c = s * 2 + a_cke;
                uint32_t addr = sa + a_rloc * 128 + ((c ^ (a_rloc & 7)) << 4);
                LDMATRIX_X4(a0, a1, a2, a3, addr);
            }
            uint32_t bL[4], bH[4];
            {
                int c = s * 2 + b_cke;
                uint32_t addr0 = sb + b_n * 128 + ((c ^ (b_n & 7)) << 4);
                LDMATRIX_X4(bL[0], bL[1], bL[2], bL[3], addr0);
                int n1 = 16 + b_n;
                uint32_t addr1 = sb + n1 * 128 + ((c ^ (n1 & 7)) << 4);
                LDMATRIX_X4(bH[0], bH[1], bH[2], bH[3], addr1);
            }
            MMA_FP8(acc[0], a0, a1, a2, a3, bL[0], bL[1]);
            MMA_FP8(acc[1], a0, a1, a2, a3, bL[2], bL[3]);
            MMA_FP8(acc[2], a0, a1, a2, a3, bH[0], bH[1]);
            MMA_FP8(acc[3], a0, a1, a2, a3, bH[2], bH[3]);
        }
    }

    if (!TRANS_OUT) {
        const int row0 = mbase + wid * 16 + (lane >> 2);
        #pragma unroll
        for (int j = 0; j < 4; j++) {
            int col = j * 8 + (lane & 3) * 2;
            *(float2*)(Out + (size_t)row0 * 32 + col) = make_float2(acc[j][0], acc[j][1]);
            *(float2*)(Out + (size_t)(row0 + 8) * 32 + col) = make_float2(acc[j][2], acc[j][3]);
        }
    } else {
        float* ep = (float*)smem;
        __syncthreads();
        const int mloc = wid * 16 + (lane >> 2);
        #pragma unroll
        for (int j = 0; j < 4; j++) {
            int col = j * 8 + (lane & 3) * 2;
            ep[col * 128 + mloc]           = acc[j][0];
            ep[(col + 1) * 128 + mloc]     = acc[j][1];
            ep[col * 128 + mloc + 8]       = acc[j][2];
            ep[(col + 1) * 128 + mloc + 8] = acc[j][3];
        }
        __syncthreads();
        #pragma unroll
        for (int i = 0; i < 16; i++) {
            int idx = tid + i * 256;
            int cc = idx >> 7, mm = idx & 127;
            Out[(size_t)cc * 8192 + mbase + mm] = ep[idx];
        }
    }
}

// z phase: zb[b][t] = e5m2( (sum_ks y)[t][b] * dot(Mp[t], r[b]) * cz )
// each CTA handles 32 t-values; g_y read via __ldcg (rewritten every hop -> L1 stale risk)
__device__ void z_phase(const float* __restrict__ Mp, int hop, float cz, uint8_t* smem) {
    float* rsh = (float*)smem;          // [32][81]
    float* zt  = rsh + 32 * 81;         // [32][33]
    int tid = threadIdx.x, w = tid >> 5, lane = tid & 31;

    for (int i = tid; i < BB * HH; i += 256) {
        int bb = i / HH, hh = i % HH;
        rsh[bb * 81 + hh] = g_h[bb * 320 + HH * (hop + 1) + hh];
    }
    __syncthreads();

    int t0 = blockIdx.x * 32;
    for (int tt = w; tt < 32; tt += 8) {
        int t = t0 + tt;
        const float* mp = Mp + (size_t)t * HH;
        float p = 0.f;
        #pragma unroll
        for (int hh = 0; hh < HH; hh++) p += mp[hh] * rsh[lane * 81 + hh];
        size_t off = (size_t)t * BB + lane;
        float ysum = 0.f;
        #pragma unroll
        for (int k = 0; k < KSPLIT; k++) ysum += __ldcg(&g_y[k][off]);
        zt[lane * 33 + tt] = ysum * p * cz;
    }
    __syncthreads();
    int b = tid >> 3, jj = (tid & 7) * 4;
    float z0 = zt[b * 33 + jj + 0];
    float z1 = zt[b * 33 + jj + 1];
    float z2 = zt[b * 33 + jj + 2];
    float z3 = zt[b * 33 + jj + 3];
    uint16_t u0, u1;
    CVT_E5M2X2(u0, z1, z0);
    CVT_E5M2X2(u1, z3, z2);
    *(uint32_t*)&g_zb[(size_t)b * TT_ + t0 + jj] = (uint32_t)u0 | ((uint32_t)u1 << 16);
}

__global__ void __launch_bounds__(256, 2) mega_kernel(const float* __restrict__ Mp,
                                                      float* __restrict__ out) {
    extern __shared__ uint8_t smem[];
    const float CZ[3] = { 8.f, 1.f / 512.f, 1.f / 1024.f };
    const float CB[3] = { 0.f, 2.f, 4.f };
    const float FX[3] = { 1.f / 33554432.f, 1.f / 2147483648.f, 1.f / 137438953472.f };
    const size_t XS = (size_t)BB * NEE;
    const int ks = blockIdx.x >> 6;

    for (int hop = 0; hop < HOPS; hop++) {
        if (hop > 0) {
            // combine phase: sum 4 xp partials of prev hop -> e5m2 g_xb
            const float* p0 = &g_xp[hop - 1][0][0];
            size_t i = (size_t)blockIdx.x * 256 + threadIdx.x;
            float4 v = __ldcg((const float4*)p0 + i);
            #pragma unroll
            for (int k = 1; k < KSPLIT; k++) {
                float4 w2 = __ldcg((const float4*)(p0 + k * XS) + i);
                v.x += w2.x; v.y += w2.y; v.z += w2.z; v.w += w2.w;
            }
            float cb = CB[hop];
            uint16_t u0, u1;
            CVT_E5M2X2(u0, v.y * cb, v.x * cb);
            CVT_E5M2X2(u1, v.w * cb, v.z * cb);
            ((uint32_t*)g_xb)[i] = (uint32_t)u0 | ((uint32_t)u1 << 16);
            grid_barrier();
        }
        // GEMM1: y = Ms @ x
        gemm_phase<false>(g_Msb, g_xb, &g_y[ks][0], smem);
        grid_barrier();
        // z
        z_phase(Mp, hop, CZ[hop], smem);
        grid_barrier();
        // GEMM2: xp[hop] = MoT @ z
        gemm_phase<true>(g_MoTb, g_zb, &g_xp[hop][ks][0], smem);
        grid_barrier();
    }

    // final phase: out[b][n] = sigmoid(sum_h attn[b][h] * x_h[b][n] * FX[h])
    #pragma unroll
    for (int j = 0; j < 4; j++) {
        int idx = blockIdx.x * 256 + threadIdx.x + j * 65536;
        int b = idx >> 13, n = idx & 8191;
        float l0 = g_att[b * 3 + 0], l1 = g_att[b * 3 + 1], l2 = g_att[b * 3 + 2];
        float m = fmaxf(l0, fmaxf(l1, l2));
        float e0 = expf(l0 - m), e1 = expf(l1 - m), e2 = expf(l2 - m);
        float inv = 1.f / (e0 + e1 + e2);
        size_t off = (size_t)b * NEE + n;
        float x0 = 0.f, x1 = 0.f, x2 = 0.f;
        #pragma unroll
        for (int k = 0; k < KSPLIT; k++) {
            x0 += g_xp[0][k][off];
            x1 += g_xp[1][k][off];
            x2 += g_xp[2][k][off];
        }
        float v = x0 * FX[0] * e0 + x1 * FX[1] * e1 + x2 * FX[2] * e2;
        out[off] = 1.f / (1.f + expf(-v * inv));
    }
}

// ---------------- launch (forked-capture multi-stream prologue + megakernel) ----------------
extern "C" void kernel_launch(void* const* d_in, const int* in_sizes, int n_in,
                              void* d_out, int out_size) {
    const float* span_embs = (const float*)d_in[0];
    const float* attention = (const float*)d_in[1];
    const float* qn_emb    = (const float*)d_in[2];
    const int*   trip_ids  = (const int*)  d_in[3];
    const int*   offsets   = (const int*)  d_in[4];
    const int*   qid_inds  = (const int*)  d_in[5];
    const float* emb_table = (const float*)d_in[6];
    const float* span_w    = (const float*)d_in[7];
    const float* span_b    = (const float*)d_in[8];
    const float* red_w     = (const float*)d_in[9];
    const float* red_b     = (const float*)d_in[10];
    const float* Ms        = (const float*)d_in[11];
    const float* Mo        = (const float*)d_in[12];
    const float* Mp        = (const float*)d_in[13];
    float* out = (float*)d_out;

    static cudaStream_t s1 = nullptr, s2 = nullptr, s3 = nullptr;
    static cudaEvent_t eF = nullptr, e1 = nullptr, e2 = nullptr, e3 = nullptr;
    if (!s1) {
        cudaStreamCreateWithFlags(&s1, cudaStreamNonBlocking);
        cudaStreamCreateWithFlags(&s2, cudaStreamNonBlocking);
        cudaStreamCreateWithFlags(&s3, cudaStreamNonBlocking);
        cudaEventCreateWithFlags(&eF, cudaEventDisableTiming);
        cudaEventCreateWithFlags(&e1, cudaEventDisableTiming);
        cudaEventCreateWithFlags(&e2, cudaEventDisableTiming);
        cudaEventCreateWithFlags(&e3, cudaEventDisableTiming);
        cudaFuncSetAttribute(mega_kernel,
                             cudaFuncAttributeMaxDynamicSharedMemorySize, GEMM_SMEM);
        cudaFuncSetAttribute(convT_kernel,
                             cudaFuncAttributeMaxDynamicSharedMemorySize, CONVT_SMEM);
    }

    const float SX0 = 256.f;

    // ---- fork ----
    cudaEventRecord(eF, 0);
    cudaStreamWaitEvent(s1, eF, 0);
    cudaStreamWaitEvent(s2, eF, 0);
    cudaStreamWaitEvent(s3, eF, 0);

    convMs_kernel<<<32768, 256, 0, s1>>>(Ms);
    convT_kernel<<<dim3(TT_ / 128, NEE / 128), dim3(32, 32), CONVT_SMEM, s2>>>(Mo);
    qr_kernel<<<BB, 256, 0, s3>>>(qn_emb, red_w, red_b,
                                  (const float*)d_in[14], (const float*)d_in[15],
                                  (const float*)d_in[16], (const float*)d_in[17],
                                  (const float*)d_in[18], (const float*)d_in[19],
                                  (const float*)d_in[20], (const float*)d_in[21],
                                  (const float*)d_in[22], (const float*)d_in[23],
                                  (const float*)d_in[24], (const float*)d_in[25]);
    emb_dot_kernel<<<BB * 16, 256>>>(emb_table, trip_ids, attention, offsets, span_embs);
    cand_softmax_kernel<<<BB, 256>>>(span_embs, span_w, span_b, qid_inds, SX0);

    // ---- join everything, then one megakernel for the whole hop loop ----
    cudaEventRecord(e1, s1);
    cudaStreamWaitEvent(0, e1, 0);
    cudaEventRecord(e2, s2);
    cudaStreamWaitEvent(0, e2, 0);
    cudaEventRecord(e3, s3);
    cudaStreamWaitEvent(0, e3, 0);

    mega_kernel<<<256, 256, GEMM_SMEM>>>(Mp, out);
}

// round 16
// speedup vs baseline: 1.1065x; 1.1065x over previous
#include <cuda_runtime.h>
#include <cuda_bf16.h>
#include <cstdint>

// ---------------- model constants ----------------
#define BB   32
#define SS   8
#define DD   768
#define NEE  8192
#define TT_  8192
#define HH   80
#define LL   2048
#define SCC  256
#define HOPS 3
#define KSPLIT 8

// ---------------- PTX helpers ----------------
__device__ __forceinline__ uint32_t smem_to_u32(const void* smem_ptr) {
    uint32_t addr;
    asm("{ .reg .u64 tmp; cvta.to.shared.u64 tmp, %1; cvt.u32.u64 %0, tmp; }"
        : "=r"(addr) : "l"(smem_ptr));
    return addr;
}
#define CP_ASYNC16(dst_u32, src_ptr) \
    asm volatile("cp.async.cg.shared.global [%0], [%1], 16;" :: "r"(dst_u32), "l"(src_ptr))
#define CP_COMMIT() asm volatile("cp.async.commit_group;" ::: "memory")
#define CP_WAIT(n)  asm volatile("cp.async.wait_group %0;" :: "n"(n) : "memory")
#define LDMATRIX_X4(r0, r1, r2, r3, addr) \
    asm volatile("ldmatrix.sync.aligned.m8n8.x4.shared.b16 {%0,%1,%2,%3}, [%4];" \
        : "=r"(r0), "=r"(r1), "=r"(r2), "=r"(r3) : "r"(addr))
#define MMA_FP8(c, a0, a1, a2, a3, b0, b1) \
    asm volatile("mma.sync.aligned.m16n8k32.row.col.f32.e4m3.e5m2.f32 " \
        "{%0,%1,%2,%3}, {%4,%5,%6,%7}, {%8,%9}, {%0,%1,%2,%3};" \
        : "+f"((c)[0]), "+f"((c)[1]), "+f"((c)[2]), "+f"((c)[3]) \
        : "r"(a0), "r"(a1), "r"(a2), "r"(a3), "r"(b0), "r"(b1))
#define CVT_E4M3X2(r, hi, lo) \
    asm("cvt.rn.satfinite.e4m3x2.f32 %0, %1, %2;" : "=h"(r) : "f"(hi), "f"(lo))
#define CVT_E5M2X2(r, hi, lo) \
    asm("cvt.rn.satfinite.e5m2x2.f32 %0, %1, %2;" : "=h"(r) : "f"(hi), "f"(lo))

#define SCALE_M 128.0f

// ---------------- scratch (device globals) ----------------
__device__ float g_sum1p[16][BB * SCC];
__device__ __align__(16) uint8_t g_xb[BB * NEE];
__device__ float g_y[KSPLIT][TT_ * BB];
__device__ __align__(16) uint8_t g_zb[BB * TT_];
__device__ float g_xp[HOPS][KSPLIT][BB * NEE];
__device__ float g_h[BB * 320];
__device__ float g_att[BB * 3];
__device__ __align__(16) uint8_t g_Msb[(size_t)TT_ * NEE];
__device__ __align__(16) uint8_t g_MoTb[(size_t)NEE * TT_];

// ---------------- Ms fp32 -> e4m3 x128 ----------------
__global__ void convMs_kernel(const float* __restrict__ Ms) {
    size_t i = (size_t)blockIdx.x * 256 + threadIdx.x;
    float4 v0 = ((const float4*)Ms)[2 * i], v1 = ((const float4*)Ms)[2 * i + 1];
    uint16_t u0, u1, u2, u3;
    CVT_E4M3X2(u0, v0.y * SCALE_M, v0.x * SCALE_M);
    CVT_E4M3X2(u1, v0.w * SCALE_M, v0.z * SCALE_M);
    CVT_E4M3X2(u2, v1.y * SCALE_M, v1.x * SCALE_M);
    CVT_E4M3X2(u3, v1.w * SCALE_M, v1.z * SCALE_M);
    uint2 o;
    o.x = (uint32_t)u0 | ((uint32_t)u1 << 16);
    o.y = (uint32_t)u2 | ((uint32_t)u3 << 16);
    ((uint2*)g_Msb)[i] = o;
}

// ---------------- convT v4: 128t x 128n tiles, conflict-free swizzle ----------------
#define CONVT_SMEM (128 * 129 * 4)
__global__ void __launch_bounds__(1024) convT_kernel(const float* __restrict__ Mo) {
    extern __shared__ float sh[];
    int t0 = blockIdx.x * 128, n0 = blockIdx.y * 128;
    int tx = threadIdx.x, ty = threadIdx.y;
    #pragma unroll
    for (int j = 0; j < 4; j++) {
        int c  = ty + 32 * j;
        int fc = (c >> 2) | ((c & 3) << 5);
        const float* src = Mo + (size_t)(t0 + c) * NEE + n0 + tx;
        #pragma unroll
        for (int nn = 0; nn < 4; nn++)
            sh[(nn * 32 + tx) * 129 + fc] = src[nn * 32];
    }
    __syncthreads();
    #pragma unroll
    for (int nn = 0; nn < 4; nn++) {
        int r = nn * 32 + ty;
        const float* row = sh + r * 129 + tx;
        float a = row[0]  * SCALE_M;
        float b = row[32] * SCALE_M;
        float c = row[64] * SCALE_M;
        float d = row[96] * SCALE_M;
        uint16_t p0, p1;
        CVT_E4M3X2(p0, b, a);
        CVT_E4M3X2(p1, d, c);
        ((uint32_t*)g_MoTb)[((size_t)(n0 + r) * TT_ + t0) / 4 + tx] =
            (uint32_t)p0 | ((uint32_t)p1 << 16);
    }
}

// ---------------- EmbeddingBag + span dot -> per-chunk partials ----------------
__device__ __forceinline__ int segsearch(const int* o, int l) {
    int lo = 0, hi = SCC;
    #pragma unroll
    for (int s = 0; s < 8; s++) {
        int mid = (lo + hi) >> 1;
        if (o[mid] <= l) lo = mid + 1; else hi = mid;
    }
    return lo - 1;
}

__global__ void __launch_bounds__(256) emb_dot_kernel(
        const float* __restrict__ emb,
        const int* __restrict__ ids,
        const float* __restrict__ att,
        const int* __restrict__ offs,
        const float* __restrict__ span_embs) {
    int b = blockIdx.x >> 4, chunk = blockIdx.x & 15;
    int tid = threadIdx.x, w = tid >> 5, lane = tid & 31;

    __shared__ float span_s[SS * DD];
    __shared__ int   offs_s[SCC];
    __shared__ float sum1_s[SCC];

    const float4* sp  = (const float4*)(span_embs + (size_t)b * SS * DD);
    float4*       sps = (float4*)span_s;
    #pragma unroll
    for (int i = 0; i < (SS * DD / 4) / 256; i++) sps[tid + i * 256] = sp[tid + i * 256];
    offs_s[tid] = offs[b * SCC + tid];
    sum1_s[tid] = 0.f;
    __syncthreads();

    const int bL   = b * LL;
    const int base = chunk * 128 + w * 16;

    #pragma unroll
    for (int i = 0; i < 16; i += 2) {
        int la = base + i, lb = base + i + 1;
        int   ida = ids[bL + la], idb = ids[bL + lb];
        float wa  = att[bL + la], wb  = att[bL + lb];
        int sega = segsearch(offs_s, la);
        int segb = segsearch(offs_s, lb);
        const float4* ra = (const float4*)(emb + (size_t)ida * DD);
        const float4* rb = (const float4*)(emb + (size_t)idb * DD);
        const float4* sa = (const float4*)(span_s + (sega & 7) * DD);
        const float4* sb = (const float4*)(span_s + (segb & 7) * DD);
        float da = 0.f, db = 0.f;
        #pragma unroll
        for (int j = 0; j < 6; j++) {
            float4 va = ra[lane + 32 * j];
            float4 xa = sa[lane + 32 * j];
            da += va.x * xa.x + va.y * xa.y + va.z * xa.z + va.w * xa.w;
            float4 vb = rb[lane + 32 * j];
            float4 xb = sb[lane + 32 * j];
            db += vb.x * xb.x + vb.y * xb.y + vb.z * xb.z + vb.w * xb.w;
        }
        #pragma unroll
        for (int o = 16; o; o >>= 1) {
            da += __shfl_xor_sync(0xffffffffu, da, o);
            db += __shfl_xor_sync(0xffffffffu, db, o);
        }
        if (lane == 0) {
            atomicAdd(&sum1_s[sega], wa * da);
            atomicAdd(&sum1_s[segb], wb * db);
        }
    }
    __syncthreads();
    g_sum1p[chunk][b * SCC + tid] = sum1_s[tid];
}

// ---------------- fused: softmax chain -> cand -> scatter -> NE softmax -> e5m2 ----------------
__global__ void cand_softmax_kernel(const float* __restrict__ span_embs,
                                    const float* __restrict__ span_w,
                                    const float* __restrict__ span_b,
                                    const int* __restrict__ qid_inds,
                                    float sx0) {
    int b = blockIdx.x, tid = threadIdx.x;
    __shared__ float ent[NEE];
    __shared__ float sh_sum1[256];
    __shared__ float sh_score[8];
    __shared__ float red[8];
    __shared__ float bc;

    #pragma unroll
    for (int i = 0; i < NEE / 256; i++) ent[tid + i * 256] = 0.f;

    int w = tid >> 5, lane = tid & 31;
    {
        const float* se = span_embs + ((size_t)b * SS + w) * DD;
        float d = 0.f;
        for (int i = lane; i < DD; i += 32) d += se[i] * span_w[i];
        #pragma unroll
        for (int o = 16; o; o >>= 1) d += __shfl_xor_sync(0xffffffffu, d, o);
        if (lane == 0) sh_score[w] = d + span_b[0];
    }
    {
        float s1v = 0.f;
        #pragma unroll
        for (int c2 = 0; c2 < 16; c2++) s1v += g_sum1p[c2][b * SCC + tid];
        sh_sum1[tid] = s1v;
    }
    __syncthreads();

    int c = tid & 31, s = tid >> 5;
    float m = -1e30f;
    #pragma unroll
    for (int s2 = 0; s2 < 8; s2++) m = fmaxf(m, sh_sum1[s2 * 32 + c]);
    float den = 0.f;
    #pragma unroll
    for (int s2 = 0; s2 < 8; s2++) den += expf(sh_sum1[s2 * 32 + c] - m);
    float sm1 = expf(sh_sum1[tid] - m) / den;
    float tv  = sh_score[s] * sm1;

    float bm = tv;
    #pragma unroll
    for (int o = 16; o; o >>= 1) bm = fmaxf(bm, __shfl_xor_sync(0xffffffffu, bm, o));
    if (lane == 0) red[w] = bm;
    __syncthreads();
    if (tid == 0) { float x = red[0]; for (int j = 1; j < 8; j++) x = fmaxf(x, red[j]); bc = x; }
    __syncthreads();
    bm = bc;
    float e = expf(tv - bm);
    float sm = e;
    #pragma unroll
    for (int o = 16; o; o >>= 1) sm += __shfl_xor_sync(0xffffffffu, sm, o);
    __syncthreads();
    if (lane == 0) red[w] = sm;
    __syncthreads();
    if (tid == 0) { float x = 0.f; for (int j = 0; j < 8; j++) x += red[j]; bc = x; }
    __syncthreads();
    float cand = e / bc;

    int qid = qid_inds[b * SCC + tid];
    if (qid < NEE) atomicAdd(&ent[qid], cand);
    __syncthreads();

    float v[NEE / 256];
    m = -1e30f;
    #pragma unroll
    for (int i = 0; i < NEE / 256; i++) { v[i] = ent[tid + i * 256]; m = fmaxf(m, v[i]); }
    #pragma unroll
    for (int o = 16; o; o >>= 1) m = fmaxf(m, __shfl_xor_sync(0xffffffffu, m, o));
    if (lane == 0) red[w] = m;
    __syncthreads();
    if (tid == 0) { float x = red[0]; for (int j = 1; j < 8; j++) x = fmaxf(x, red[j]); bc = x; }
    __syncthreads();
    m = bc;
    float ssum = 0.f;
    #pragma unroll
    for (int i = 0; i < NEE / 256; i++) { v[i] = expf(v[i] - m); ssum += v[i]; }
    #pragma unroll
    for (int o = 16; o; o >>= 1) ssum += __shfl_xor_sync(0xffffffffu, ssum, o);
    __syncthreads();
    if (lane == 0) red[w] = ssum;
    __syncthreads();
    if (tid == 0) { float x = 0.f; for (int j = 0; j < 8; j++) x += red[j]; bc = x; }
    __syncthreads();
    float inv = sx0 / bc;
    uint8_t* orow = g_xb + (size_t)b * NEE;
    #pragma unroll
    for (int i = 0; i < NEE / 256; i++) {
        uint16_t pk; CVT_E5M2X2(pk, 0.f, v[i] * inv);
        orow[tid + i * 256] = (uint8_t)(pk & 0xff);
    }
}

// ---------------- combine KSPLIT split x partials -> e5m2 g_xb ----------------
__global__ void combine_xb_kernel(const float* __restrict__ p0, float cb) {
    size_t i = (size_t)blockIdx.x * 256 + threadIdx.x;
    const size_t XS = (size_t)BB * NEE;
    float4 v = ((const float4*)p0)[i];
    #pragma unroll
    for (int k = 1; k < KSPLIT; k++) {
        float4 w2 = ((const float4*)(p0 + k * XS))[i];
        v.x += w2.x; v.y += w2.y; v.z += w2.z; v.w += w2.w;
    }
    uint16_t u0, u1;
    CVT_E5M2X2(u0, v.y * cb, v.x * cb);
    CVT_E5M2X2(u1, v.w * cb, v.z * cb);
    ((uint32_t*)g_xb)[i] = (uint32_t)u0 | ((uint32_t)u1 << 16);
}

// ---------------- fused q + all 3 r-hops + att logits (256 threads) ----------------
__global__ void qr_kernel(const float* __restrict__ qn,
                          const float* __restrict__ rw,
                          const float* __restrict__ rb,
                          const float* __restrict__ iw0, const float* __restrict__ ib0,
                          const float* __restrict__ iw1, const float* __restrict__ ib1,
                          const float* __restrict__ iw2, const float* __restrict__ ib2,
                          const float* __restrict__ aw0, const float* __restrict__ ab0,
                          const float* __restrict__ aw1, const float* __restrict__ ab1,
                          const float* __restrict__ aw2, const float* __restrict__ ab2) {
    int b = blockIdx.x, tid = threadIdx.x;
    int w = tid >> 5, lane = tid & 31;
    __shared__ float h[320];
    __shared__ float v[80];

    const float* q = qn + (size_t)b * DD;
    for (int hh = w; hh < HH; hh += 8) {
        const float* r = rw + (size_t)hh * DD;
        float d = 0.f;
        for (int i = lane; i < DD; i += 32) d += q[i] * r[i];
        #pragma unroll
        for (int o = 16; o; o >>= 1) d += __shfl_xor_sync(0xffffffffu, d, o);
        if (lane == 0) h[hh] = d + rb[hh];
    }
    __syncthreads();

    const float* IW[3] = {iw0, iw1, iw2};
    const float* IB[3] = {ib0, ib1, ib2};
    const float* AW[3] = {aw0, aw1, aw2};
    const float* AB[3] = {ab0, ab1, ab2};

    for (int hop = 0; hop < HOPS; hop++) {
        int Wd = HH * (hop + 1);
        if (tid < 80) {
            float a = IB[hop][tid];
            const float* row = IW[hop] + (size_t)tid * Wd;
            for (int i = 0; i < Wd; i++) a += h[i] * row[i];
            v[tid] = a;
        } else if (tid == 80) {
            float a = AB[hop][0];
            for (int i = 0; i < Wd; i++) a += h[i] * AW[hop][i];
            g_att[b * 3 + hop] = a;
        }
        __syncthreads();
        float m = -1e30f;
        for (int i = 0; i < 80; i++) m = fmaxf(m, v[i]);
        float s = 0.f;
        for (int i = 0; i < 80; i++) s += expf(v[i] - m);
        if (tid < 80) h[Wd + tid] = expf(v[tid] - m) / s;
        __syncthreads();
    }
    for (int i = tid; i < 320; i += 256) g_h[b * 320 + i] = h[i];
}

// =====================================================================
// FP8 MMA GEMM: split-K x8 (1024 K each), grid 512
//   3-stage cp.async pipeline (60KB smem -> 3 CTAs/SM)
// =====================================================================
#define KCHUNK 128
#define NIT    8
#define SA_STAGE 16384
#define SB_STAGE 4096
#define GEMM_SMEM (3 * (SA_STAGE + SB_STAGE))   // 61440

template<bool TRANS_OUT>
__global__ void __launch_bounds__(256) fp8_gemm_kernel(
    const uint8_t* __restrict__ A,
    const uint8_t* __restrict__ Bb,
    float* __restrict__ OutBase, size_t out_split_stride) {

    extern __shared__ uint8_t smem[];
    const uint32_t sAb = smem_to_u32(smem);
    const uint32_t sBb = sAb + 3 * SA_STAGE;

    const int tid  = threadIdx.x;
    const int wid  = tid >> 5;
    const int lane = tid & 31;
    const int mbase  = blockIdx.x * 128;
    const int kstart = blockIdx.y * (KCHUNK * NIT);
    float* Out = OutBase + blockIdx.y * out_split_stride;

    const uint8_t* Ab = A + (size_t)mbase * 8192 + kstart;
    const uint8_t* Bx = Bb + kstart;

    const int arow = tid >> 3;
    const int ac   = tid & 7;
    auto prefetch = [&](int it) {
        const int stage = it % 3;
        const uint32_t sa = sAb + stage * SA_STAGE;
        const uint32_t sb = sBb + stage * SB_STAGE;
        const uint8_t* ga = Ab + it * KCHUNK;
        #pragma unroll
        for (int j = 0; j < 4; j++) {
            int row = arow + j * 32;
            uint32_t dst = sa + row * 128 + ((ac ^ (row & 7)) << 4);
            CP_ASYNC16(dst, ga + (size_t)row * 8192 + ac * 16);
        }
        uint32_t dstb = sb + arow * 128 + ((ac ^ (arow & 7)) << 4);
        CP_ASYNC16(dstb, Bx + (size_t)arow * 8192 + it * KCHUNK + ac * 16);
    };

    prefetch(0); CP_COMMIT();
    prefetch(1); CP_COMMIT();

    float acc[4][4];
    #pragma unroll
    for (int j = 0; j < 4; j++)
        #pragma unroll
        for (int i = 0; i < 4; i++) acc[j][i] = 0.f;

    const int a_quad = lane >> 3;
    const int a_rloc = wid * 16 + (lane & 7) + (a_quad & 1) * 8;
    const int a_cke  = a_quad >> 1;
    const int b_n    = ((lane >> 4) * 8) + (lane & 7);
    const int b_cke  = (lane >> 3) & 1;

    for (int it = 0; it < NIT; it++) {
        if (it + 1 < NIT) { CP_WAIT(1); }
        else { CP_WAIT(0); }
        __syncthreads();
        if (it + 2 < NIT) { prefetch(it + 2); CP_COMMIT(); }

        const int stage = it % 3;
        const uint32_t sa = sAb + stage * SA_STAGE;
        const uint32_t sb = sBb + stage * SB_STAGE;

        #pragma unroll
        for (int s = 0; s < 4; s++) {
            uint32_t a0, a1, a2, a3;
            {
                int c = s * 2 + a_cke;
                uint32_t addr = sa + a_rloc * 128 + ((c ^ (a_rloc & 7)) << 4);
                LDMATRIX_X4(a0, a1, a2, a3, addr);
            }
            uint32_t bL[4], bH[4];
            {
                int c = s * 2 + b_cke;
                uint32_t addr0 = sb + b_n * 128 + ((c ^ (b_n & 7)) << 4);
                LDMATRIX_X4(bL[0], bL[1], bL[2], bL[3], addr0);
                int n1 = 16 + b_n;
                uint32_t addr1 = sb + n1 * 128 + ((c ^ (n1 & 7)) << 4);
                LDMATRIX_X4(bH[0], bH[1], bH[2], bH[3], addr1);
            }
            MMA_FP8(acc[0], a0, a1, a2, a3, bL[0], bL[1]);
            MMA_FP8(acc[1], a0, a1, a2, a3, bL[2], bL[3]);
            MMA_FP8(acc[2], a0, a1, a2, a3, bH[0], bH[1]);
            MMA_FP8(acc[3], a0, a1, a2, a3, bH[2], bH[3]);
        }
    }

    if (!TRANS_OUT) {
        const int row0 = mbase + wid * 16 + (lane >> 2);
        #pragma unroll
        for (int j = 0; j < 4; j++) {
            int col = j * 8 + (lane & 3) * 2;
            *(float2*)(Out + (size_t)row0 * 32 + col) = make_float2(acc[j][0], acc[j][1]);
            *(float2*)(Out + (size_t)(row0 + 8) * 32 + col) = make_float2(acc[j][2], acc[j][3]);
        }
    } else {
        float* ep = (float*)smem;
        __syncthreads();
        const int mloc = wid * 16 + (lane >> 2);
        #pragma unroll
        for (int j = 0; j < 4; j++) {
            int col = j * 8 + (lane & 3) * 2;
            ep[col * 128 + mloc]           = acc[j][0];
            ep[(col + 1) * 128 + mloc]     = acc[j][1];
            ep[col * 128 + mloc + 8]       = acc[j][2];
            ep[(col + 1) * 128 + mloc + 8] = acc[j][3];
        }
        __syncthreads();
        #pragma unroll
        for (int i = 0; i < 16; i++) {
            int idx = tid + i * 256;
            int cc = idx >> 7, mm = idx & 127;
            Out[(size_t)cc * 8192 + mbase + mm] = ep[idx];
        }
    }
}

// ---------------- z: zb[b][t] = e5m2( (sum_ks y)[t][b] * dot(Mp[t], r[b]) * cz ) ----------------
__global__ void z_kernel(const float* __restrict__ Mp, int hop, float cz) {
    __shared__ float rsh[32][81];
    __shared__ float ztile[32][8];
    int tid = threadIdx.x;
    for (int i = tid; i < BB * HH; i += 256) {
        int bb = i / HH, h = i % HH;
        rsh[bb][h] = g_h[bb * 320 + HH * (hop + 1) + h];
    }
    __syncthreads();
    int w = tid >> 5, lane = tid & 31;
    int t = blockIdx.x * 8 + w;
    const float* mp = Mp + (size_t)t * HH;
    float p = 0.f;
    #pragma unroll
    for (int h = 0; h < HH; h++) p += mp[h] * rsh[lane][h];
    size_t off = (size_t)t * BB + lane;
    float ysum = 0.f;
    #pragma unroll
    for (int k = 0; k < KSPLIT; k++) ysum += g_y[k][off];
    ztile[lane][w] = ysum * p * cz;
    __syncthreads();
    int b = tid >> 3, j = tid & 7;
    uint16_t pk; CVT_E5M2X2(pk, 0.f, ztile[b][j]);
    g_zb[(size_t)b * TT_ + blockIdx.x * 8 + j] = (uint8_t)(pk & 0xff);
}

// ---------------- final ----------------
__global__ void final_kernel(float* __restrict__ out, float f0, float f1, float f2) {
    int b = blockIdx.y;
    int n = blockIdx.x * 256 + threadIdx.x;
    float l0 = g_att[b * 3 + 0], l1 = g_att[b * 3 + 1], l2 = g_att[b * 3 + 2];
    float m = fmaxf(l0, fmaxf(l1, l2));
    float e0 = expf(l0 - m), e1 = expf(l1 - m), e2 = expf(l2 - m);
    float inv = 1.f / (e0 + e1 + e2);
    size_t off = (size_t)b * NEE + n;
    float x0 = 0.f, x1 = 0.f, x2 = 0.f;
    #pragma unroll
    for (int k = 0; k < KSPLIT; k++) {
        x0 += g_xp[0][k][off];
        x1 += g_xp[1][k][off];
        x2 += g_xp[2][k][off];
    }
    float v = x0 * f0 * e0 + x1 * f1 * e1 + x2 * f2 * e2;
    out[off] = 1.f / (1.f + expf(-v * inv));
}

// ---------------- launch (forked capture; convs serialized on s1) ----------------
extern "C" void kernel_launch(void* const* d_in, const int* in_sizes, int n_in,
                              void* d_out, int out_size) {
    const float* span_embs = (const float*)d_in[0];
    const float* attention = (const float*)d_in[1];
    const float* qn_emb    = (const float*)d_in[2];
    const int*   trip_ids  = (const int*)  d_in[3];
    const int*   offsets   = (const int*)  d_in[4];
    const int*   qid_inds  = (const int*)  d_in[5];
    const float* emb_table = (const float*)d_in[6];
    const float* span_w    = (const float*)d_in[7];
    const float* span_b    = (const float*)d_in[8];
    const float* red_w     = (const float*)d_in[9];
    const float* red_b     = (const float*)d_in[10];
    const float* Ms        = (const float*)d_in[11];
    const float* Mo        = (const float*)d_in[12];
    const float* Mp        = (const float*)d_in[13];
    float* out = (float*)d_out;

    static cudaStream_t s1 = nullptr, s3 = nullptr;
    static cudaEvent_t eF = nullptr, e1 = nullptr, e2 = nullptr, e3 = nullptr;
    if (!s1) {
        cudaStreamCreateWithFlags(&s1, cudaStreamNonBlocking);
        cudaStreamCreateWithFlags(&s3, cudaStreamNonBlocking);
        cudaEventCreateWithFlags(&eF, cudaEventDisableTiming);
        cudaEventCreateWithFlags(&e1, cudaEventDisableTiming);
        cudaEventCreateWithFlags(&e2, cudaEventDisableTiming);
        cudaEventCreateWithFlags(&e3, cudaEventDisableTiming);
        cudaFuncSetAttribute(fp8_gemm_kernel<false>,
                             cudaFuncAttributeMaxDynamicSharedMemorySize, GEMM_SMEM);
        cudaFuncSetAttribute(fp8_gemm_kernel<true>,
                             cudaFuncAttributeMaxDynamicSharedMemorySize, GEMM_SMEM);
        cudaFuncSetAttribute(convT_kernel,
                             cudaFuncAttributeMaxDynamicSharedMemorySize, CONVT_SMEM);
    }

    float *py, *pxp;
    cudaGetSymbolAddress((void**)&py,  g_y);
    cudaGetSymbolAddress((void**)&pxp, g_xp);
    uint8_t *pMsb, *pMoT, *pxb, *pzb;
    cudaGetSymbolAddress((void**)&pMsb, g_Msb);
    cudaGetSymbolAddress((void**)&pMoT, g_MoTb);
    cudaGetSymbolAddress((void**)&pxb,  g_xb);
    cudaGetSymbolAddress((void**)&pzb,  g_zb);

    const size_t YS = (size_t)TT_ * BB;
    const size_t XS = (size_t)BB * NEE;

    const float SX0 = 256.f;
    const float CZ[3] = { 8.f, 1.f / 512.f, 1.f / 1024.f };
    const float CB[3] = { 0.f, 2.f, 4.f };
    const float FX[3] = { 1.f / 33554432.f, 1.f / 2147483648.f, 1.f / 137438953472.f };

    // ---- fork ----
    cudaEventRecord(eF, 0);
    cudaStreamWaitEvent(s1, eF, 0);
    cudaStreamWaitEvent(s3, eF, 0);

    // s1: convMs FIRST (GEMM1 gate), then convT (GEMM2 gate) — serialized so
    // convMs gets full bandwidth and GEMM1 can start ~50us earlier.
    convMs_kernel<<<32768, 256, 0, s1>>>(Ms);
    cudaEventRecord(e1, s1);
    convT_kernel<<<dim3(TT_ / 128, NEE / 128), dim3(32, 32), CONVT_SMEM, s1>>>(Mo);
    cudaEventRecord(e2, s1);

    // s3: q + r-chain
    qr_kernel<<<BB, 256, 0, s3>>>(qn_emb, red_w, red_b,
                                  (const float*)d_in[14], (const float*)d_in[15],
                                  (const float*)d_in[16], (const float*)d_in[17],
                                  (const float*)d_in[18], (const float*)d_in[19],
                                  (const float*)d_in[20], (const float*)d_in[21],
                                  (const float*)d_in[22], (const float*)d_in[23],
                                  (const float*)d_in[24], (const float*)d_in[25]);
    cudaEventRecord(e3, s3);

    // default stream: embedding + candidate/entity softmax chain
    emb_dot_kernel<<<BB * 16, 256>>>(emb_table, trip_ids, attention, offsets, span_embs);
    cand_softmax_kernel<<<BB, 256>>>(span_embs, span_w, span_b, qid_inds, SX0);

    // GEMM1 hop0 only needs Msb + xb
    cudaStreamWaitEvent(0, e1, 0);
    fp8_gemm_kernel<false><<<dim3(64, KSPLIT), 256, GEMM_SMEM>>>(pMsb, pxb, py, YS);

    // z needs qr; GEMM2 needs MoT
    cudaStreamWaitEvent(0, e3, 0);
    cudaStreamWaitEvent(0, e2, 0);

    for (int hop = 0; hop < HOPS; hop++) {
        if (hop > 0) {
            combine_xb_kernel<<<256, 256>>>(pxp + (size_t)(hop - 1) * KSPLIT * XS, CB[hop]);
            fp8_gemm_kernel<false><<<dim3(64, KSPLIT), 256, GEMM_SMEM>>>(pMsb, pxb, py, YS);
        }
        z_kernel<<<TT_ / 8, 256>>>(Mp, hop, CZ[hop]);
        fp8_gemm_kernel<true><<<dim3(64, KSPLIT), 256, GEMM_SMEM>>>(
            pMoT, pzb, pxp + (size_t)hop * KSPLIT * XS, XS);
    }
    final_kernel<<<dim3(NEE / 256, BB), 256>>>(out, FX[0], FX[1], FX[2]);
}